// round 13
// baseline (speedup 1.0000x reference)
#include <cuda_runtime.h>
#include <cuda_bf16.h>
#include <mma.h>

using namespace nvcuda;

#define N_GROUPS 256
#define EMBED 1024
#define VEC4 (EMBED / 4)   // 256 float4 per row
#define LOSS_BLOCKS 64

// Scratch (device globals; no allocation allowed)
__device__ __nv_bfloat16 g_im_bf16[N_GROUPS * EMBED];
__device__ __nv_bfloat16 g_s_bf16[N_GROUPS * EMBED];
__device__ float g_S[N_GROUPS * N_GROUPS];   // 256 KB
__device__ float g_loss_part[LOSS_BLOCKS];
__device__ int   g_count;   // zero at load; reset by last block each launch

// ---------------------------------------------------------------------------
// Kernel 1: segment mean -> bf16. Grid = 2048 blocks of 64 threads.
//   blockIdx.x = g*8 + src*4 + quarter. Thread owns one float4 column of its
//   quarter-row; 8-deep register-batched LDG.128. (R7/R11-proven structure)
// ---------------------------------------------------------------------------
__global__ void __launch_bounds__(64) segmean_kernel(
    const float* __restrict__ im, const float* __restrict__ s,
    const int* __restrict__ num_clips, const int* __restrict__ num_caps)
{
    const int b = blockIdx.x;
    const int g = b >> 3;
    const bool is_im = ((b >> 2) & 1) == 0;
    const int quarter = b & 3;
    const int* __restrict__ cnt = is_im ? num_clips : num_caps;
    const float4* __restrict__ src = (const float4*)(is_im ? im : s);
    __nv_bfloat162* __restrict__ dst = (__nv_bfloat162*)(is_im ? g_im_bf16 : g_s_bf16);

    const int t = threadIdx.x;

    // start = sum of counts with index < g (4 counts/thread, 2-warp reduce)
    int contrib = 0;
    #pragma unroll
    for (int u = 0; u < 4; u++) {
        int k = t + u * 64;
        int c = cnt[k];
        contrib += (k < g) ? c : 0;
    }
    #pragma unroll
    for (int o = 16; o; o >>= 1) contrib += __shfl_xor_sync(0xFFFFFFFFu, contrib, o);
    __shared__ int ws[2];
    if ((t & 31) == 0) ws[t >> 5] = contrib;
    __syncthreads();
    const int start = ws[0] + ws[1];
    const int n = cnt[g];
    const float inv = 1.0f / (float)n;

    const float4* p = src + (size_t)start * VEC4 + quarter * 64 + t;

    float ax = 0.f, ay = 0.f, az = 0.f, aw = 0.f;
    int r = 0;
    for (; r + 8 <= n; r += 8) {
        float4 x0 = p[(size_t)(r + 0) * VEC4];
        float4 x1 = p[(size_t)(r + 1) * VEC4];
        float4 x2 = p[(size_t)(r + 2) * VEC4];
        float4 x3 = p[(size_t)(r + 3) * VEC4];
        float4 x4 = p[(size_t)(r + 4) * VEC4];
        float4 x5 = p[(size_t)(r + 5) * VEC4];
        float4 x6 = p[(size_t)(r + 6) * VEC4];
        float4 x7 = p[(size_t)(r + 7) * VEC4];
        ax += (x0.x + x1.x) + (x2.x + x3.x) + ((x4.x + x5.x) + (x6.x + x7.x));
        ay += (x0.y + x1.y) + (x2.y + x3.y) + ((x4.y + x5.y) + (x6.y + x7.y));
        az += (x0.z + x1.z) + (x2.z + x3.z) + ((x4.z + x5.z) + (x6.z + x7.z));
        aw += (x0.w + x1.w) + (x2.w + x3.w) + ((x4.w + x5.w) + (x6.w + x7.w));
    }
    if (r + 4 <= n) {
        float4 x0 = p[(size_t)(r + 0) * VEC4];
        float4 x1 = p[(size_t)(r + 1) * VEC4];
        float4 x2 = p[(size_t)(r + 2) * VEC4];
        float4 x3 = p[(size_t)(r + 3) * VEC4];
        ax += (x0.x + x1.x) + (x2.x + x3.x);
        ay += (x0.y + x1.y) + (x2.y + x3.y);
        az += (x0.z + x1.z) + (x2.z + x3.z);
        aw += (x0.w + x1.w) + (x2.w + x3.w);
        r += 4;
    }
    for (; r < n; r++) {
        float4 x0 = p[(size_t)r * VEC4];
        ax += x0.x; ay += x0.y; az += x0.z; aw += x0.w;
    }

    // mean -> bf16 pair stores (8 bytes per thread)
    float2 lo = make_float2(ax * inv, ay * inv);
    float2 hi = make_float2(az * inv, aw * inv);
    const size_t o2 = (size_t)g * (EMBED / 2) + (quarter * 64 + t) * 2;
    dst[o2 + 0] = __float22bfloat162_rn(lo);
    dst[o2 + 1] = __float22bfloat162_rn(hi);
}

// ---------------------------------------------------------------------------
// Kernel 2: S = IMmean @ SMean^T on tensor cores (bf16 in, fp32 accum).
// Grid (16,16) x 32 threads: each warp owns one 16x16 output tile,
// K=1024 in 16-wide fragment steps, fragments loaded straight from gmem
// (each fragment is L2-hot: reused by 16 blocks along the other axis).
// ---------------------------------------------------------------------------
__global__ void __launch_bounds__(32) gemm_kernel()
{
    const int bi = blockIdx.y * 16;
    const int bj = blockIdx.x * 16;

    wmma::fragment<wmma::accumulator, 16, 16, 16, float> acc;
    wmma::fill_fragment(acc, 0.0f);
    wmma::fragment<wmma::matrix_a, 16, 16, 16, __nv_bfloat16, wmma::row_major> af;
    wmma::fragment<wmma::matrix_b, 16, 16, 16, __nv_bfloat16, wmma::col_major> bf;

    const __nv_bfloat16* A = g_im_bf16 + (size_t)bi * EMBED;
    const __nv_bfloat16* B = g_s_bf16 + (size_t)bj * EMBED;

    #pragma unroll 4
    for (int k = 0; k < EMBED; k += 16) {
        wmma::load_matrix_sync(af, A + k, EMBED);
        wmma::load_matrix_sync(bf, B + k, EMBED);
        wmma::mma_sync(acc, af, bf, acc);
    }

    wmma::store_matrix_sync(&g_S[(size_t)bi * N_GROUPS + bj], acc,
                            N_GROUPS, wmma::mem_row_major);
}

// ---------------------------------------------------------------------------
// Kernel 3: hinge loss. 64 blocks x 256 threads; diag read from S;
// last-block-arrival final reduction (fixed order, deterministic).
// loss = sum_{i != j} [ max(S_ij - S_ii, 0) + max(S_ij - S_jj, 0) ]
// ---------------------------------------------------------------------------
__global__ void __launch_bounds__(256) fused_loss_kernel(float* __restrict__ out)
{
    __shared__ float diag_s[N_GROUPS];
    __shared__ float red[8];
    __shared__ int is_last;

    const int t = threadIdx.x;
    const int b = blockIdx.x;

    if (t < N_GROUPS) diag_s[t] = g_S[(size_t)t * (N_GROUPS + 1)];
    __syncthreads();

    const int q = b * 256 + t;          // 0..16383
    float4 v = *(const float4*)&g_S[(size_t)q * 4];

    const int i = q >> 6;
    const int j0 = (q & 63) * 4;
    const float di = diag_s[i];
    float vv[4] = {v.x, v.y, v.z, v.w};
    float sum = 0.f;
    #pragma unroll
    for (int c = 0; c < 4; c++) {
        const int j = j0 + c;
        if (j != i)
            sum += fmaxf(vv[c] - di, 0.f) + fmaxf(vv[c] - diag_s[j], 0.f);
    }

    #pragma unroll
    for (int o = 16; o; o >>= 1) sum += __shfl_xor_sync(0xFFFFFFFFu, sum, o);
    if ((t & 31) == 0) red[t >> 5] = sum;
    __syncthreads();

    if (t == 0) {
        float bs = red[0] + red[1] + red[2] + red[3]
                 + red[4] + red[5] + red[6] + red[7];
        g_loss_part[b] = bs;
        __threadfence();
        int old = atomicAdd(&g_count, 1);
        is_last = (old == LOSS_BLOCKS - 1) ? 1 : 0;
    }
    __syncthreads();

    if (is_last) {
        if (t < 64) {
            float v2 = __ldcg(&g_loss_part[t]);
            #pragma unroll
            for (int o = 16; o; o >>= 1) v2 += __shfl_xor_sync(0xFFFFFFFFu, v2, o);
            if (t == 0)  red[0] = v2;
            if (t == 32) red[1] = v2;
        }
        __syncthreads();
        if (t == 0) {
            out[0] = red[0] + red[1];
            g_count = 0;                 // reset for next replay
        }
    }
}

extern "C" void kernel_launch(void* const* d_in, const int* in_sizes, int n_in,
                              void* d_out, int out_size)
{
    const float* im        = (const float*)d_in[0];
    const float* s         = (const float*)d_in[1];
    const int*   num_clips = (const int*)d_in[2];
    const int*   num_caps  = (const int*)d_in[3];
    float* out = (float*)d_out;

    segmean_kernel<<<2048, 64>>>(im, s, num_clips, num_caps);
    gemm_kernel<<<dim3(16, 16), 32>>>();
    fused_loss_kernel<<<LOSS_BLOCKS, 256>>>(out);
}